// round 1
// baseline (speedup 1.0000x reference)
#include <cuda_runtime.h>
#include <math.h>
#include <stdint.h>

// Problem constants
#define BB   4
#define LSEQ 4096
#define DD   1024
#define NLBL 8921
#define NLP  8960          // NLBL padded to multiple of 256
#define NSEG 8
#define SEGL (LSEQ / NSEG) // 512

// ---------------- scratch (device globals; no allocation allowed) ----------
__device__ float g_l1[(size_t)BB * LSEQ * DD];        // 64 MB
__device__ float g_scores[(size_t)BB * LSEQ * NLBL];  // 585 MB
__device__ float g_pmax[BB * NSEG * NLP];
__device__ float g_psum[BB * NSEG * NLP];
__device__ float g_max [BB * NLP];
__device__ float g_rsum[BB * NLP];

// ---------------------------------------------------------------------------
// SGEMM: C[M,N] = A[M,K] * op(B), fp32, 128x128 block tile, BK=8, 8x8/thread.
// B_IS_NT = true : B is [N,K] row-major (dot rows of A with rows of B)
// B_IS_NT = false: B is [K,N] row-major (normal A@B)
// Optional tanh epilogue. blockIdx.z = batch (strides in elements).
// ---------------------------------------------------------------------------
template <bool B_IS_NT, bool DO_TANH>
__global__ __launch_bounds__(256) void sgemm128(
    const float* __restrict__ A, const float* __restrict__ Bm,
    float* __restrict__ C, int M, int N, int K,
    long sAb, long sBb, long sCb)
{
    const int BM = 128, BN = 128, BK = 8, TM = 8, TN = 8;
    A  += (long)blockIdx.z * sAb;
    Bm += (long)blockIdx.z * sBb;
    C  += (long)blockIdx.z * sCb;

    __shared__ float As[BK * BM];   // transposed: As[k][m]
    __shared__ float Bs[BK * BN];   // Bs[k][n]

    const int tid  = threadIdx.x;
    const int row0 = blockIdx.y * BM;
    const int col0 = blockIdx.x * BN;
    const int tRow = (tid / 16) * TM;
    const int tCol = (tid % 16) * TN;

    // A tile load mapping: 128 rows x 8 k, one float4 along K per thread
    const int aRow = tid >> 1;
    const int aCol = (tid & 1) * 4;
    // B tile (NT): 128 n-rows x 8 k
    const int bRowNT = tid >> 1;
    const int bColNT = (tid & 1) * 4;
    // B tile (NN): 8 k-rows x 128 n
    const int bRowNN = tid >> 5;
    const int bColNN = (tid & 31) * 4;

    float acc[TM][TN];
    #pragma unroll
    for (int i = 0; i < TM; i++)
        #pragma unroll
        for (int j = 0; j < TN; j++) acc[i][j] = 0.f;

    for (int k0 = 0; k0 < K; k0 += BK) {
        // ---- load A tile (guard M; K is a multiple of BK and 16B-aligned) ----
        float4 av = make_float4(0.f, 0.f, 0.f, 0.f);
        if (row0 + aRow < M)
            av = *reinterpret_cast<const float4*>(&A[(long)(row0 + aRow) * K + k0 + aCol]);
        As[(aCol + 0) * BM + aRow] = av.x;
        As[(aCol + 1) * BM + aRow] = av.y;
        As[(aCol + 2) * BM + aRow] = av.z;
        As[(aCol + 3) * BM + aRow] = av.w;

        // ---- load B tile ----
        if (B_IS_NT) {
            float4 bv = make_float4(0.f, 0.f, 0.f, 0.f);
            if (col0 + bRowNT < N)
                bv = *reinterpret_cast<const float4*>(&Bm[(long)(col0 + bRowNT) * K + k0 + bColNT]);
            Bs[(bColNT + 0) * BN + bRowNT] = bv.x;
            Bs[(bColNT + 1) * BN + bRowNT] = bv.y;
            Bs[(bColNT + 2) * BN + bRowNT] = bv.z;
            Bs[(bColNT + 3) * BN + bRowNT] = bv.w;
        } else {
            float4 bv = make_float4(0.f, 0.f, 0.f, 0.f);
            if (col0 + bColNN + 3 < N)
                bv = *reinterpret_cast<const float4*>(&Bm[(long)(k0 + bRowNN) * N + col0 + bColNN]);
            *reinterpret_cast<float4*>(&Bs[bRowNN * BN + bColNN]) = bv;
        }
        __syncthreads();

        // ---- compute ----
        #pragma unroll
        for (int k = 0; k < BK; k++) {
            float ra[TM], rb[TN];
            #pragma unroll
            for (int i = 0; i < TM; i++) ra[i] = As[k * BM + tRow + i];
            #pragma unroll
            for (int j = 0; j < TN; j++) rb[j] = Bs[k * BN + tCol + j];
            #pragma unroll
            for (int i = 0; i < TM; i++)
                #pragma unroll
                for (int j = 0; j < TN; j++)
                    acc[i][j] = fmaf(ra[i], rb[j], acc[i][j]);
        }
        __syncthreads();
    }

    // ---- epilogue ----
    #pragma unroll
    for (int i = 0; i < TM; i++) {
        int r = row0 + tRow + i;
        if (r >= M) continue;
        #pragma unroll
        for (int j = 0; j < TN; j++) {
            int c = col0 + tCol + j;
            if (c >= N) continue;
            float v = acc[i][j];
            if (DO_TANH) v = tanhf(v);
            C[(long)r * N + c] = v;
        }
    }
}

// ---------------------------------------------------------------------------
// Softmax over the L dimension of scores[B, L, NL], segmented for occupancy.
// Pass 1: per-(b, seg, n) online max/sumexp. Coalesced over n.
// ---------------------------------------------------------------------------
__global__ void softmax_part(const float* __restrict__ scores)
{
    int n = blockIdx.x * 256 + threadIdx.x;   // < NLP
    int s = blockIdx.y;
    int b = blockIdx.z;
    float m = -1e30f, sum = 0.f;
    if (n < NLBL) {
        const float* p = scores + ((size_t)b * LSEQ + (size_t)s * SEGL) * NLBL + n;
        #pragma unroll 4
        for (int l = 0; l < SEGL; l++) {
            float v = p[(size_t)l * NLBL];
            if (v <= m) {
                sum += __expf(v - m);
            } else {
                sum = sum * __expf(m - v) + 1.f;
                m = v;
            }
        }
    }
    g_pmax[(b * NSEG + s) * NLP + n] = m;
    g_psum[(b * NSEG + s) * NLP + n] = sum;
}

// Pass 2: combine segments -> per-(b,n) max and 1/sum
__global__ void softmax_comb()
{
    int n = blockIdx.x * 256 + threadIdx.x;
    int b = blockIdx.z;
    float m = -1e30f;
    #pragma unroll
    for (int s = 0; s < NSEG; s++)
        m = fmaxf(m, g_pmax[(b * NSEG + s) * NLP + n]);
    float sum = 0.f;
    #pragma unroll
    for (int s = 0; s < NSEG; s++)
        sum += g_psum[(b * NSEG + s) * NLP + n] * __expf(g_pmax[(b * NSEG + s) * NLP + n] - m);
    g_max [b * NLP + n] = m;
    g_rsum[b * NLP + n] = 1.f / sum;
}

// ---------------------------------------------------------------------------
// attn[b, n, l] = exp(scores[b, l, n] - max[b,n]) * rsum[b,n]
// 32x32 smem transpose: read coalesced over n, write coalesced over l.
// ---------------------------------------------------------------------------
__global__ void attn_transpose(const float* __restrict__ scores, float* __restrict__ attn)
{
    __shared__ float tile[32][33];
    int b  = blockIdx.z;
    int n0 = blockIdx.x * 32;
    int l0 = blockIdx.y * 32;
    int tx = threadIdx.x, ty = threadIdx.y;  // 32 x 8

    int n = n0 + tx;
    float m = 0.f, r = 0.f;
    if (n < NLBL) {
        m = g_max [b * NLP + n];
        r = g_rsum[b * NLP + n];
    }
    #pragma unroll
    for (int i = 0; i < 4; i++) {
        int l = l0 + ty + i * 8;
        float v = 0.f;
        if (n < NLBL)
            v = __expf(scores[((size_t)b * LSEQ + l) * NLBL + n] - m) * r;
        tile[ty + i * 8][tx] = v;
    }
    __syncthreads();
    #pragma unroll
    for (int i = 0; i < 4; i++) {
        int n2 = n0 + ty + i * 8;
        int l  = l0 + tx;
        if (n2 < NLBL)
            attn[((size_t)b * NLBL + n2) * LSEQ + l] = tile[tx][ty + i * 8];
    }
}

// ---------------------------------------------------------------------------
extern "C" void kernel_launch(void* const* d_in, const int* in_sizes, int n_in,
                              void* d_out, int out_size)
{
    const float* x  = (const float*)d_in[0];   // [B, L, D]
    const float* W1 = (const float*)d_in[1];   // [D, D]
    const float* W2 = (const float*)d_in[2];   // [NL, D]

    float* out  = (float*)d_out;                          // [B, NL, D]
    float* attn = out + (size_t)BB * NLBL * DD;           // [B, NL, L]

    float *l1, *scores;
    cudaGetSymbolAddress((void**)&l1, g_l1);
    cudaGetSymbolAddress((void**)&scores, g_scores);

    dim3 blk(256);

    // 1) l1 = tanh(x @ W1^T)   M=B*L, N=D, K=D  (NT)
    sgemm128<true, true><<<dim3(DD / 128, (BB * LSEQ) / 128, 1), blk>>>(
        x, W1, l1, BB * LSEQ, DD, DD, 0, 0, 0);

    // 2) scores = l1 @ W2^T    M=B*L, N=NL, K=D (NT)
    sgemm128<true, false><<<dim3((NLBL + 127) / 128, (BB * LSEQ) / 128, 1), blk>>>(
        l1, W2, scores, BB * LSEQ, NLBL, DD, 0, 0, 0);

    // 3) column softmax stats over L
    softmax_part<<<dim3(NLP / 256, NSEG, BB), 256>>>(scores);
    softmax_comb<<<dim3(NLP / 256, 1, BB), 256>>>();

    // 4) attn = softmax(scores).T (per batch), normalized + transposed
    attn_transpose<<<dim3((NLBL + 31) / 32, LSEQ / 32, BB), dim3(32, 8)>>>(scores, attn);

    // 5) out[b] = attn[b] @ x[b]   M=NL, N=D, K=L (NN), batched over z
    sgemm128<false, false><<<dim3(DD / 128, (NLBL + 127) / 128, BB), blk>>>(
        attn, x, out, NLBL, DD, LSEQ,
        (long)NLBL * LSEQ, (long)LSEQ * DD, (long)NLBL * DD);
}

// round 3
// speedup vs baseline: 3.8534x; 3.8534x over previous
#include <cuda_runtime.h>
#include <math.h>
#include <stdint.h>

// Problem constants
#define BB   4
#define LSEQ 4096
#define DD   1024
#define NLBL 8921
#define NLP  8960          // padded label count (multiple of 128/256)
#define NSEG 8
#define SEGL (LSEQ / NSEG) // 512

// GEMM tiling
#define Bb   128           // BM
#define BN   128
#define BK   32
#define STAGES 3
#define STG_FLOATS (2 * Bb * BK)              // A + B per stage = 8192 floats
#define SMEM_FLOATS (STAGES * STG_FLOATS)     // 24576 floats = 96 KB

// ---------------- scratch (device globals; no allocation allowed) ----------
__device__ float g_l1[(size_t)BB * LSEQ * DD];         // 64 MB: l1, then xT
__device__ float g_scores[(size_t)BB * LSEQ * NLP];    // 587 MB
__device__ float g_attnr[(size_t)BB * NLP * LSEQ];     // 587 MB rounded+padded attn
__device__ float g_xr [(size_t)BB * LSEQ * DD];        // 64 MB rounded x
__device__ float g_w1r[(size_t)DD * DD];               // 4 MB
__device__ float g_w2r[(size_t)NLP * DD];              // 36.7 MB rounded+padded W2
__device__ float g_pmax[BB * NSEG * NLP];
__device__ float g_psum[BB * NSEG * NLP];
__device__ float g_max [BB * NLP];
__device__ float g_rsum[BB * NLP];

// ======================= helpers ===========================================
__device__ __forceinline__ uint32_t smem_u32(const void* p) {
    uint32_t a;
    asm("{ .reg .u64 t; cvta.to.shared.u64 t, %1; cvt.u32.u64 %0, t; }"
        : "=r"(a) : "l"(p));
    return a;
}
__device__ __forceinline__ float f_rna_tf32(float v) {
    uint32_t r;
    asm("cvt.rna.tf32.f32 %0, %1;" : "=r"(r) : "f"(v));
    return __uint_as_float(r);
}
__device__ __forceinline__ void cp_async16(uint32_t dst, const void* src) {
    asm volatile("cp.async.cg.shared.global [%0], [%1], 16;"
        :: "r"(dst), "l"(src));
}
#define CP_COMMIT() asm volatile("cp.async.commit_group;" ::: "memory")
#define CP_WAIT(n)  asm volatile("cp.async.wait_group %0;" :: "n"(n) : "memory")

__device__ __forceinline__ void mma_tf32(float* c, const uint32_t* a, const uint32_t* b) {
    asm volatile(
        "mma.sync.aligned.m16n8k8.row.col.f32.tf32.tf32.f32 "
        "{%0,%1,%2,%3}, {%4,%5,%6,%7}, {%8,%9}, {%0,%1,%2,%3};"
        : "+f"(c[0]), "+f"(c[1]), "+f"(c[2]), "+f"(c[3])
        : "r"(a[0]), "r"(a[1]), "r"(a[2]), "r"(a[3]),
          "r"(b[0]), "r"(b[1]));
}

// smem float offset for element (r, k) of a 128x32 tile; XOR swizzle keeps
// 16B cp.async chunks intact and makes all fragment LDS.32 conflict-free.
__device__ __forceinline__ int swoff(int r, int k) {
    return (r << 5) + (k ^ ((r & 7) << 2));
}

// ---------------------------------------------------------------------------
// tf32 mma.sync GEMM (NT): C[M x Nc] = A[M x K] @ B[* x K]^T
// A has >= gridDim.y*128 rows, B has >= gridDim.x*128 rows (padded, unguarded).
// Output rows guarded to Mv. blockIdx.z = batch via element strides.
// DO_TANH: epilogue v = rna_tf32(tanh(v)) (for l1).
// ---------------------------------------------------------------------------
template <bool DO_TANH, bool GUARD_M>
__global__ __launch_bounds__(256, 2) void tc_gemm(
    const float* __restrict__ A, const float* __restrict__ Bm, float* __restrict__ C,
    int Mv, int Nc, int K, long sAb, long sBb, long sCb)
{
    extern __shared__ float smf[];
    const int tid  = threadIdx.x;
    const int wid  = tid >> 5;
    const int lid  = tid & 31;
    const int g    = lid >> 2;   // group id (0..7)
    const int tig  = lid & 3;    // thread in group
    const int wrow = wid >> 1;   // 0..3  (M direction, 32 rows each)
    const int wcol = wid & 1;    // 0..1  (N direction, 64 cols each)

    A  += (long)blockIdx.z * sAb;
    Bm += (long)blockIdx.z * sBb;
    C  += (long)blockIdx.z * sCb;

    const long row0 = (long)blockIdx.y * Bb;
    const long col0 = (long)blockIdx.x * BN;
    const int  nch  = K / BK;

    // per-thread tile-load mapping: 1024 float4 per operand, 4 per thread
    const int lr = tid >> 3;        // base row (stride 32 over t)
    const int lc = tid & 7;         // float4 column

    float acc[2][8][4];
    #pragma unroll
    for (int mt = 0; mt < 2; mt++)
        #pragma unroll
        for (int nt = 0; nt < 8; nt++)
            #pragma unroll
            for (int q = 0; q < 4; q++) acc[mt][nt][q] = 0.f;

    const uint32_t sbase = smem_u32(smf);

    // issue one stage's cp.asyncs
    auto issue = [&](int i, int s) {
        const float* Ag = A + row0 * K + (long)i * BK;
        const float* Bg = Bm + col0 * K + (long)i * BK;
        uint32_t st = sbase + s * (STG_FLOATS * 4);
        #pragma unroll
        for (int t = 0; t < 4; t++) {
            int r = lr + t * 32;
            int dst = swoff(r, lc * 4) * 4;
            cp_async16(st + dst, Ag + (long)r * K + lc * 4);
        }
        uint32_t stB = st + Bb * BK * 4;
        #pragma unroll
        for (int t = 0; t < 4; t++) {
            int r = lr + t * 32;
            int dst = swoff(r, lc * 4) * 4;
            cp_async16(stB + dst, Bg + (long)r * K + lc * 4);
        }
    };

    #pragma unroll
    for (int i = 0; i < STAGES - 1; i++) { issue(i, i); CP_COMMIT(); }

    for (int i = 0; i < nch; i++) {
        CP_WAIT(STAGES - 2);
        __syncthreads();

        const int inext = i + STAGES - 1;
        if (inext < nch) issue(inext, inext % STAGES);
        CP_COMMIT();

        const uint32_t* sA = reinterpret_cast<const uint32_t*>(
            smf + (i % STAGES) * STG_FLOATS);
        const uint32_t* sB = sA + Bb * BK;

        #pragma unroll
        for (int ks = 0; ks < 4; ks++) {
            const int kb = ks * 8;
            uint32_t af[2][4], bf[8][2];
            #pragma unroll
            for (int mt = 0; mt < 2; mt++) {
                int ra = wrow * 32 + mt * 16 + g;
                af[mt][0] = sA[swoff(ra,     kb + tig)];
                af[mt][1] = sA[swoff(ra + 8, kb + tig)];
                af[mt][2] = sA[swoff(ra,     kb + tig + 4)];
                af[mt][3] = sA[swoff(ra + 8, kb + tig + 4)];
            }
            #pragma unroll
            for (int nt = 0; nt < 8; nt++) {
                int rb = wcol * 64 + nt * 8 + g;
                bf[nt][0] = sB[swoff(rb, kb + tig)];
                bf[nt][1] = sB[swoff(rb, kb + tig + 4)];
            }
            #pragma unroll
            for (int mt = 0; mt < 2; mt++)
                #pragma unroll
                for (int nt = 0; nt < 8; nt++)
                    mma_tf32(acc[mt][nt], af[mt], bf[nt]);
        }
        __syncthreads();
    }

    // epilogue: float2 stores, rows g and g+8 per m-tile
    #pragma unroll
    for (int mt = 0; mt < 2; mt++) {
        long r0 = row0 + wrow * 32 + mt * 16 + g;
        long r1 = r0 + 8;
        bool ok0 = !GUARD_M || (r0 < Mv);
        bool ok1 = !GUARD_M || (r1 < Mv);
        #pragma unroll
        for (int nt = 0; nt < 8; nt++) {
            long cc = col0 + wcol * 64 + nt * 8 + 2 * tig;
            float2 v0 = make_float2(acc[mt][nt][0], acc[mt][nt][1]);
            float2 v1 = make_float2(acc[mt][nt][2], acc[mt][nt][3]);
            if (DO_TANH) {
                v0.x = f_rna_tf32(tanhf(v0.x)); v0.y = f_rna_tf32(tanhf(v0.y));
                v1.x = f_rna_tf32(tanhf(v1.x)); v1.y = f_rna_tf32(tanhf(v1.y));
            }
            if (ok0) *reinterpret_cast<float2*>(&C[r0 * Nc + cc]) = v0;
            if (ok1) *reinterpret_cast<float2*>(&C[r1 * Nc + cc]) = v1;
        }
    }
}

// ---------------------------------------------------------------------------
// pre-round helpers
// ---------------------------------------------------------------------------
__global__ void roundcpy(const float* __restrict__ src, float* __restrict__ dst, int n)
{
    int i = blockIdx.x * 256 + threadIdx.x;
    if (i < n) dst[i] = f_rna_tf32(src[i]);
}
__global__ void w2pad(const float* __restrict__ W2, float* __restrict__ dst)
{
    int i = blockIdx.x * 256 + threadIdx.x;
    if (i >= NLP * DD) return;
    int row = i / DD;
    dst[i] = (row < NLBL) ? f_rna_tf32(W2[i]) : 0.f;
}

// ---------------------------------------------------------------------------
// Softmax over L of scores[B, L, NLP] (valid cols < NLBL), segmented.
// ---------------------------------------------------------------------------
__global__ void softmax_part(const float* __restrict__ scores)
{
    int n = blockIdx.x * 256 + threadIdx.x;
    int s = blockIdx.y;
    int b = blockIdx.z;
    float m = -1e30f, sum = 0.f;
    if (n < NLBL) {
        const float* p = scores + ((size_t)b * LSEQ + (size_t)s * SEGL) * NLP + n;
        #pragma unroll 4
        for (int l = 0; l < SEGL; l++) {
            float v = p[(size_t)l * NLP];
            if (v <= m) {
                sum += __expf(v - m);
            } else {
                sum = sum * __expf(m - v) + 1.f;
                m = v;
            }
        }
    }
    g_pmax[(b * NSEG + s) * NLP + n] = m;
    g_psum[(b * NSEG + s) * NLP + n] = sum;
}

__global__ void softmax_comb()
{
    int n = blockIdx.x * 256 + threadIdx.x;
    int b = blockIdx.z;
    float m = -1e30f;
    #pragma unroll
    for (int s = 0; s < NSEG; s++)
        m = fmaxf(m, g_pmax[(b * NSEG + s) * NLP + n]);
    float sum = 0.f;
    #pragma unroll
    for (int s = 0; s < NSEG; s++)
        sum += g_psum[(b * NSEG + s) * NLP + n] * __expf(g_pmax[(b * NSEG + s) * NLP + n] - m);
    g_max [b * NLP + n] = m;
    g_rsum[b * NLP + n] = 1.f / sum;
}

// ---------------------------------------------------------------------------
// attn[b,n,l] = exp(scores[b,l,n]-max)*rsum; exact copy to output,
// rounded+padded copy to g_attnr for GEMM3. Grid covers NLP columns.
// ---------------------------------------------------------------------------
__global__ void attn_transpose(const float* __restrict__ scores,
                               float* __restrict__ attn, float* __restrict__ attnr)
{
    __shared__ float tile[32][33];
    int b  = blockIdx.z;
    int n0 = blockIdx.x * 32;
    int l0 = blockIdx.y * 32;
    int tx = threadIdx.x, ty = threadIdx.y;  // 32 x 8

    int n = n0 + tx;
    float m = 0.f, r = 0.f;
    if (n < NLBL) {
        m = g_max [b * NLP + n];
        r = g_rsum[b * NLP + n];
    }
    #pragma unroll
    for (int i = 0; i < 4; i++) {
        int l = l0 + ty + i * 8;
        float v = 0.f;
        if (n < NLBL)
            v = __expf(scores[((size_t)b * LSEQ + l) * NLP + n] - m) * r;
        tile[ty + i * 8][tx] = v;
    }
    __syncthreads();
    #pragma unroll
    for (int i = 0; i < 4; i++) {
        int n2 = n0 + ty + i * 8;
        int l  = l0 + tx;
        float v = tile[tx][ty + i * 8];
        if (n2 < NLBL)
            attn[((size_t)b * NLBL + n2) * LSEQ + l] = v;
        attnr[((size_t)b * NLP + n2) * LSEQ + l] = (n2 < NLBL) ? f_rna_tf32(v) : 0.f;
    }
}

// ---------------------------------------------------------------------------
// xT[b][d][l] = rna_tf32(x[b][l][d])
// ---------------------------------------------------------------------------
__global__ void xpose(const float* __restrict__ x, float* __restrict__ xT)
{
    __shared__ float tile[32][33];
    int b  = blockIdx.z;
    int d0 = blockIdx.x * 32;
    int l0 = blockIdx.y * 32;
    int tx = threadIdx.x, ty = threadIdx.y;  // 32 x 8
    #pragma unroll
    for (int i = 0; i < 4; i++)
        tile[ty + i * 8][tx] = x[((size_t)b * LSEQ + l0 + ty + i * 8) * DD + d0 + tx];
    __syncthreads();
    #pragma unroll
    for (int i = 0; i < 4; i++)
        xT[((size_t)b * DD + d0 + ty + i * 8) * LSEQ + l0 + tx] =
            f_rna_tf32(tile[tx][ty + i * 8]);
}

// ---------------------------------------------------------------------------
extern "C" void kernel_launch(void* const* d_in, const int* in_sizes, int n_in,
                              void* d_out, int out_size)
{
    const float* x  = (const float*)d_in[0];   // [B, L, D]
    const float* W1 = (const float*)d_in[1];   // [D, D]
    const float* W2 = (const float*)d_in[2];   // [NL, D]

    float* out  = (float*)d_out;                          // [B, NL, D]
    float* attn = out + (size_t)BB * NLBL * DD;           // [B, NL, L]

    float *l1, *scores, *attnr, *xr, *w1r, *w2r;
    cudaGetSymbolAddress((void**)&l1, g_l1);
    cudaGetSymbolAddress((void**)&scores, g_scores);
    cudaGetSymbolAddress((void**)&attnr, g_attnr);
    cudaGetSymbolAddress((void**)&xr, g_xr);
    cudaGetSymbolAddress((void**)&w1r, g_w1r);
    cudaGetSymbolAddress((void**)&w2r, g_w2r);

    const int SMEMB = SMEM_FLOATS * 4;  // 96 KB
    cudaFuncSetAttribute(tc_gemm<true,  false>, cudaFuncAttributeMaxDynamicSharedMemorySize, SMEMB);
    cudaFuncSetAttribute(tc_gemm<false, false>, cudaFuncAttributeMaxDynamicSharedMemorySize, SMEMB);
    cudaFuncSetAttribute(tc_gemm<false, true >, cudaFuncAttributeMaxDynamicSharedMemorySize, SMEMB);

    // 0) pre-round operands to tf32 values (RNA)
    roundcpy<<<(BB * LSEQ * DD + 255) / 256, 256>>>(x, xr, BB * LSEQ * DD);
    roundcpy<<<(DD * DD + 255) / 256, 256>>>(W1, w1r, DD * DD);
    w2pad<<<(NLP * DD + 255) / 256, 256>>>(W2, w2r);

    // 1) l1 = rna(tanh(xr @ w1r^T)):  M=16384, N=1024, K=1024
    tc_gemm<true, false><<<dim3(DD / BN, (BB * LSEQ) / Bb, 1), 256, SMEMB>>>(
        xr, w1r, l1, BB * LSEQ, DD, DD, 0, 0, 0);

    // 2) scores = l1 @ w2r^T:  M=16384, Nc=NLP, K=1024
    tc_gemm<false, false><<<dim3(NLP / BN, (BB * LSEQ) / Bb, 1), 256, SMEMB>>>(
        l1, w2r, scores, BB * LSEQ, NLP, DD, 0, 0, 0);

    // 3) xT = rna(transpose(x)) into g_l1 (l1 dead after GEMM2)
    xpose<<<dim3(DD / 32, LSEQ / 32, BB), dim3(32, 8)>>>(x, l1);

    // 4) column softmax stats over L
    softmax_part<<<dim3(NLP / 256, NSEG, BB), 256>>>(scores);
    softmax_comb<<<dim3(NLP / 256, 1, BB), 256>>>();

    // 5) attn (exact) + attnr (rounded, padded)
    attn_transpose<<<dim3(NLP / 32, LSEQ / 32, BB), dim3(32, 8)>>>(scores, attn, attnr);

    // 6) out[b] = attnr[b] @ xT[b]^T:  M=NLP(->NLBL), N=1024, K=4096
    tc_gemm<false, true><<<dim3(DD / BN, NLP / Bb, BB), 256, SMEMB>>>(
        attnr, l1, out, NLBL, DD, LSEQ,
        (long)NLP * LSEQ, (long)DD * LSEQ, (long)NLBL * DD);
}

// round 4
// speedup vs baseline: 4.5613x; 1.1837x over previous
#include <cuda_runtime.h>
#include <math.h>
#include <stdint.h>

// Problem constants
#define BB   4
#define LSEQ 4096
#define DD   1024
#define NLBL 8921
#define NLP  8960          // padded label count (multiple of 128/256)
#define NSEG 8
#define SEGL (LSEQ / NSEG) // 512

// GEMM tiling
#define Bb   128           // BM
#define BN   128
#define BK   32
#define STAGES 3
#define STG_FLOATS (2 * Bb * BK)              // A + B per stage = 8192 floats
#define SMEM_FLOATS (STAGES * STG_FLOATS)     // 24576 floats = 96 KB

// ---------------- scratch (device globals; no allocation allowed) ----------
__device__ float g_l1[(size_t)BB * LSEQ * DD];         // 64 MB: l1, then xT
__device__ float g_scores[(size_t)BB * LSEQ * NLP];    // 587 MB
__device__ float g_xr [(size_t)BB * LSEQ * DD];        // 64 MB rounded x
__device__ float g_w1r[(size_t)DD * DD];               // 4 MB
__device__ float g_w2r[(size_t)NLP * DD];              // 36.7 MB rounded+padded W2
__device__ float g_pmax[BB * NSEG * NLP];
__device__ float g_psum[BB * NSEG * NLP];
__device__ float g_max [BB * NLP];
__device__ float g_rsum[BB * NLP];

// ======================= helpers ===========================================
__device__ __forceinline__ uint32_t smem_u32(const void* p) {
    uint32_t a;
    asm("{ .reg .u64 t; cvta.to.shared.u64 t, %1; cvt.u32.u64 %0, t; }"
        : "=r"(a) : "l"(p));
    return a;
}
__device__ __forceinline__ float f_rna_tf32(float v) {
    uint32_t r;
    asm("cvt.rna.tf32.f32 %0, %1;" : "=r"(r) : "f"(v));
    return __uint_as_float(r);
}
__device__ __forceinline__ void cp_async16(uint32_t dst, const void* src) {
    asm volatile("cp.async.cg.shared.global [%0], [%1], 16;"
        :: "r"(dst), "l"(src));
}
#define CP_COMMIT() asm volatile("cp.async.commit_group;" ::: "memory")
#define CP_WAIT(n)  asm volatile("cp.async.wait_group %0;" :: "n"(n) : "memory")

__device__ __forceinline__ void mma_tf32(float* c, const uint32_t* a, const uint32_t* b) {
    asm volatile(
        "mma.sync.aligned.m16n8k8.row.col.f32.tf32.tf32.f32 "
        "{%0,%1,%2,%3}, {%4,%5,%6,%7}, {%8,%9}, {%0,%1,%2,%3};"
        : "+f"(c[0]), "+f"(c[1]), "+f"(c[2]), "+f"(c[3])
        : "r"(a[0]), "r"(a[1]), "r"(a[2]), "r"(a[3]),
          "r"(b[0]), "r"(b[1]));
}

// ldmatrix x4 of 8x8 b16 tiles == four (8 row x 4 col) b32 mma quadrants
__device__ __forceinline__ void ldsm4(uint32_t& r0, uint32_t& r1,
                                      uint32_t& r2, uint32_t& r3, uint32_t addr) {
    asm volatile("ldmatrix.sync.aligned.m8n8.x4.shared.b16 {%0,%1,%2,%3}, [%4];"
        : "=r"(r0), "=r"(r1), "=r"(r2), "=r"(r3) : "r"(addr));
}

// smem float offset for element (r, k) of a 128x32 tile; XOR swizzle keeps
// 16B chunks intact and makes all fragment reads bank-conflict-free.
__device__ __forceinline__ int swoff(int r, int k) {
    return (r << 5) + (k ^ ((r & 7) << 2));
}

// ---------------------------------------------------------------------------
// tf32 mma.sync GEMM (NT): C[M x Nc] = A[M x K] @ B[* x K]^T
// B rows padded to grid width (unguarded). A rows clamped if CLAMP_A.
// Output rows guarded to Mv if GUARD_M. blockIdx.z = batch via strides.
// ---------------------------------------------------------------------------
template <bool DO_TANH, bool GUARD_M, bool CLAMP_A>
__global__ __launch_bounds__(256, 2) void tc_gemm(
    const float* __restrict__ A, const float* __restrict__ Bm, float* __restrict__ C,
    int Mv, int Nc, int K, long sAb, long sBb, long sCb)
{
    extern __shared__ float smf[];
    const uint32_t sbase = smem_u32(smf);
    const int tid  = threadIdx.x;
    const int wid  = tid >> 5;
    const int lid  = tid & 31;
    const int g    = lid >> 2;
    const int tig  = lid & 3;
    const int wrow = wid >> 1;   // 0..3 (M, 32 rows each)
    const int wcol = wid & 1;    // 0..1 (N, 64 cols each)

    A  += (long)blockIdx.z * sAb;
    Bm += (long)blockIdx.z * sBb;
    C  += (long)blockIdx.z * sCb;

    const long row0 = (long)blockIdx.y * Bb;
    const long col0 = (long)blockIdx.x * BN;
    const int  nch  = K / BK;

    // tile-load mapping: 1024 float4 per operand, 4 per thread
    const int lr = tid >> 3;
    const int lc = tid & 7;

    // ldmatrix lane geometry (tile index = lid>>3)
    const int a_rin = ((lid >> 3) & 1) * 8 + (lid & 7);
    const int a_kg  = (lid >> 4) * 4;           // lanes 16-31 -> k+4
    const int b_rin = ((lid >> 4) & 1) * 8 + (lid & 7);
    const int b_kg  = ((lid >> 3) & 1) * 4;

    float acc[2][8][4];
    #pragma unroll
    for (int mt = 0; mt < 2; mt++)
        #pragma unroll
        for (int nt = 0; nt < 8; nt++)
            #pragma unroll
            for (int q = 0; q < 4; q++) acc[mt][nt][q] = 0.f;

    auto issue = [&](int i, int s) {
        const float* Ag = A + (long)i * BK;
        const float* Bg = Bm + col0 * K + (long)i * BK;
        uint32_t st = sbase + s * (STG_FLOATS * 4);
        #pragma unroll
        for (int t = 0; t < 4; t++) {
            int r = lr + t * 32;
            long rA = row0 + r;
            if (CLAMP_A && rA > Mv - 1) rA = Mv - 1;
            cp_async16(st + swoff(r, lc * 4) * 4, Ag + rA * K + lc * 4);
        }
        uint32_t stB = st + Bb * BK * 4;
        #pragma unroll
        for (int t = 0; t < 4; t++) {
            int r = lr + t * 32;
            cp_async16(stB + swoff(r, lc * 4) * 4, Bg + (long)r * K + lc * 4);
        }
    };

    #pragma unroll
    for (int i = 0; i < STAGES - 1; i++) { issue(i, i); CP_COMMIT(); }

    for (int i = 0; i < nch; i++) {
        CP_WAIT(STAGES - 2);
        __syncthreads();

        const int inext = i + STAGES - 1;
        if (inext < nch) issue(inext, inext % STAGES);
        CP_COMMIT();

        const uint32_t sAu = sbase + (i % STAGES) * (STG_FLOATS * 4);
        const uint32_t sBu = sAu + Bb * BK * 4;

        #pragma unroll
        for (int ks = 0; ks < 4; ks++) {
            const int kb = ks * 8;
            uint32_t af[2][4], bf[8][2];
            #pragma unroll
            for (int mt = 0; mt < 2; mt++) {
                int r = wrow * 32 + mt * 16 + a_rin;
                ldsm4(af[mt][0], af[mt][1], af[mt][2], af[mt][3],
                      sAu + 4u * swoff(r, kb + a_kg));
            }
            #pragma unroll
            for (int j = 0; j < 4; j++) {
                int r = wcol * 64 + j * 16 + b_rin;
                ldsm4(bf[2 * j][0], bf[2 * j][1], bf[2 * j + 1][0], bf[2 * j + 1][1],
                      sBu + 4u * swoff(r, kb + b_kg));
            }
            #pragma unroll
            for (int mt = 0; mt < 2; mt++)
                #pragma unroll
                for (int nt = 0; nt < 8; nt++)
                    mma_tf32(acc[mt][nt], af[mt], bf[nt]);
        }
    }

    // epilogue: float2 stores, rows g and g+8 per m-tile
    #pragma unroll
    for (int mt = 0; mt < 2; mt++) {
        long r0 = row0 + wrow * 32 + mt * 16 + g;
        long r1 = r0 + 8;
        bool ok0 = !GUARD_M || (r0 < Mv);
        bool ok1 = !GUARD_M || (r1 < Mv);
        #pragma unroll
        for (int nt = 0; nt < 8; nt++) {
            long cc = col0 + wcol * 64 + nt * 8 + 2 * tig;
            float2 v0 = make_float2(acc[mt][nt][0], acc[mt][nt][1]);
            float2 v1 = make_float2(acc[mt][nt][2], acc[mt][nt][3]);
            if (DO_TANH) {
                v0.x = f_rna_tf32(tanhf(v0.x)); v0.y = f_rna_tf32(tanhf(v0.y));
                v1.x = f_rna_tf32(tanhf(v1.x)); v1.y = f_rna_tf32(tanhf(v1.y));
            }
            if (ok0) *reinterpret_cast<float2*>(&C[r0 * Nc + cc]) = v0;
            if (ok1) *reinterpret_cast<float2*>(&C[r1 * Nc + cc]) = v1;
        }
    }
}

// ---------------------------------------------------------------------------
// pre-round helpers
// ---------------------------------------------------------------------------
__global__ void roundcpy(const float* __restrict__ src, float* __restrict__ dst, int n)
{
    int i = blockIdx.x * 256 + threadIdx.x;
    if (i < n) dst[i] = f_rna_tf32(src[i]);
}
__global__ void w2pad(const float* __restrict__ W2, float* __restrict__ dst)
{
    int i = blockIdx.x * 256 + threadIdx.x;
    if (i >= NLP * DD) return;
    int row = i / DD;
    dst[i] = (row < NLBL) ? f_rna_tf32(W2[i]) : 0.f;
}

// ---------------------------------------------------------------------------
// Softmax over L of scores[B, L, NLP] (valid cols < NLBL), segmented.
// ---------------------------------------------------------------------------
__global__ void softmax_part(const float* __restrict__ scores)
{
    int n = blockIdx.x * 256 + threadIdx.x;
    int s = blockIdx.y;
    int b = blockIdx.z;
    float m = -1e30f, sum = 0.f;
    if (n < NLBL) {
        const float* p = scores + ((size_t)b * LSEQ + (size_t)s * SEGL) * NLP + n;
        #pragma unroll 4
        for (int l = 0; l < SEGL; l++) {
            float v = p[(size_t)l * NLP];
            if (v <= m) {
                sum += __expf(v - m);
            } else {
                sum = sum * __expf(m - v) + 1.f;
                m = v;
            }
        }
    }
    g_pmax[(b * NSEG + s) * NLP + n] = m;
    g_psum[(b * NSEG + s) * NLP + n] = sum;
}

__global__ void softmax_comb()
{
    int n = blockIdx.x * 256 + threadIdx.x;
    int b = blockIdx.z;
    float m = -1e30f;
    #pragma unroll
    for (int s = 0; s < NSEG; s++)
        m = fmaxf(m, g_pmax[(b * NSEG + s) * NLP + n]);
    float sum = 0.f;
    #pragma unroll
    for (int s = 0; s < NSEG; s++)
        sum += g_psum[(b * NSEG + s) * NLP + n] * __expf(g_pmax[(b * NSEG + s) * NLP + n] - m);
    g_max [b * NLP + n] = m;
    g_rsum[b * NLP + n] = 1.f / sum;
}

// ---------------------------------------------------------------------------
// attn[b,n,l] = rna_tf32(exp(scores[b,l,n]-max)*rsum)  (single rounded copy;
// feeds both the output comparison and GEMM3)
// ---------------------------------------------------------------------------
__global__ void attn_transpose(const float* __restrict__ scores, float* __restrict__ attn)
{
    __shared__ float tile[32][33];
    int b  = blockIdx.z;
    int n0 = blockIdx.x * 32;
    int l0 = blockIdx.y * 32;
    int tx = threadIdx.x, ty = threadIdx.y;  // 32 x 8

    int n = n0 + tx;
    float m = 0.f, r = 0.f;
    if (n < NLBL) {
        m = g_max [b * NLP + n];
        r = g_rsum[b * NLP + n];
    }
    #pragma unroll
    for (int i = 0; i < 4; i++) {
        int l = l0 + ty + i * 8;
        float v = 0.f;
        if (n < NLBL)
            v = __expf(scores[((size_t)b * LSEQ + l) * NLP + n] - m) * r;
        tile[ty + i * 8][tx] = v;
    }
    __syncthreads();
    #pragma unroll
    for (int i = 0; i < 4; i++) {
        int n2 = n0 + ty + i * 8;
        int l  = l0 + tx;
        if (n2 < NLBL)
            attn[((size_t)b * NLBL + n2) * LSEQ + l] = f_rna_tf32(tile[tx][ty + i * 8]);
    }
}

// ---------------------------------------------------------------------------
// xT[b][d][l] = rna_tf32(x[b][l][d])
// ---------------------------------------------------------------------------
__global__ void xpose(const float* __restrict__ x, float* __restrict__ xT)
{
    __shared__ float tile[32][33];
    int b  = blockIdx.z;
    int d0 = blockIdx.x * 32;
    int l0 = blockIdx.y * 32;
    int tx = threadIdx.x, ty = threadIdx.y;  // 32 x 8
    #pragma unroll
    for (int i = 0; i < 4; i++)
        tile[ty + i * 8][tx] = x[((size_t)b * LSEQ + l0 + ty + i * 8) * DD + d0 + tx];
    __syncthreads();
    #pragma unroll
    for (int i = 0; i < 4; i++)
        xT[((size_t)b * DD + d0 + ty + i * 8) * LSEQ + l0 + tx] =
            f_rna_tf32(tile[tx][ty + i * 8]);
}

// ---------------------------------------------------------------------------
extern "C" void kernel_launch(void* const* d_in, const int* in_sizes, int n_in,
                              void* d_out, int out_size)
{
    const float* x  = (const float*)d_in[0];   // [B, L, D]
    const float* W1 = (const float*)d_in[1];   // [D, D]
    const float* W2 = (const float*)d_in[2];   // [NL, D]

    float* out  = (float*)d_out;                          // [B, NL, D]
    float* attn = out + (size_t)BB * NLBL * DD;           // [B, NL, L]

    float *l1, *scores, *xr, *w1r, *w2r;
    cudaGetSymbolAddress((void**)&l1, g_l1);
    cudaGetSymbolAddress((void**)&scores, g_scores);
    cudaGetSymbolAddress((void**)&xr, g_xr);
    cudaGetSymbolAddress((void**)&w1r, g_w1r);
    cudaGetSymbolAddress((void**)&w2r, g_w2r);

    const int SMEMB = SMEM_FLOATS * 4;  // 96 KB
    cudaFuncSetAttribute(tc_gemm<true,  false, false>, cudaFuncAttributeMaxDynamicSharedMemorySize, SMEMB);
    cudaFuncSetAttribute(tc_gemm<false, false, false>, cudaFuncAttributeMaxDynamicSharedMemorySize, SMEMB);
    cudaFuncSetAttribute(tc_gemm<false, true,  true >, cudaFuncAttributeMaxDynamicSharedMemorySize, SMEMB);

    // 0) pre-round operands to tf32 values (RNA)
    roundcpy<<<(BB * LSEQ * DD + 255) / 256, 256>>>(x, xr, BB * LSEQ * DD);
    roundcpy<<<(DD * DD + 255) / 256, 256>>>(W1, w1r, DD * DD);
    w2pad<<<(NLP * DD + 255) / 256, 256>>>(W2, w2r);

    // 1) l1 = rna(tanh(xr @ w1r^T)):  M=16384, N=1024, K=1024
    tc_gemm<true, false, false><<<dim3(DD / BN, (BB * LSEQ) / Bb, 1), 256, SMEMB>>>(
        xr, w1r, l1, BB * LSEQ, DD, DD, 0, 0, 0);

    // 2) scores = l1 @ w2r^T:  M=16384, Nc=NLP, K=1024
    tc_gemm<false, false, false><<<dim3(NLP / BN, (BB * LSEQ) / Bb, 1), 256, SMEMB>>>(
        l1, w2r, scores, BB * LSEQ, NLP, DD, 0, 0, 0);

    // 3) xT = rna(transpose(x)) into g_l1 (l1 dead after GEMM2)
    xpose<<<dim3(DD / 32, LSEQ / 32, BB), dim3(32, 8)>>>(x, l1);

    // 4) column softmax stats over L
    softmax_part<<<dim3(NLP / 256, NSEG, BB), 256>>>(scores);
    softmax_comb<<<dim3(NLP / 256, 1, BB), 256>>>();

    // 5) attn = rna(softmax(scores)^T)  (single rounded copy, is the output)
    attn_transpose<<<dim3(NLP / 32, LSEQ / 32, BB), dim3(32, 8)>>>(scores, attn);

    // 6) out[b] = attn[b] @ xT[b]^T:  M=8921 (rows clamped), N=1024, K=4096
    tc_gemm<false, true, true><<<dim3(DD / BN, NLP / Bb, BB), 256, SMEMB>>>(
        attn, l1, out, NLBL, DD, LSEQ,
        (long)NLBL * LSEQ, (long)DD * LSEQ, (long)NLBL * DD);
}

// round 5
// speedup vs baseline: 4.5809x; 1.0043x over previous
#include <cuda_runtime.h>
#include <math.h>
#include <stdint.h>

// Problem constants
#define BB   4
#define LSEQ 4096
#define DD   1024
#define NLBL 8921
#define NLP  8960          // padded label count (multiple of 128/256)
#define NSEG 8
#define SEGL (LSEQ / NSEG) // 512

// GEMM tiling
#define Bb   128           // BM
#define BN   128
#define BK   32
#define STAGES 3
#define STG_FLOATS (2 * Bb * BK)              // A + B per stage = 8192 floats
#define SMEM_FLOATS (STAGES * STG_FLOATS)     // 24576 floats = 96 KB

// ---------------- scratch (device globals; no allocation allowed) ----------
__device__ float g_l1[(size_t)BB * LSEQ * DD];         // 64 MB
__device__ float g_scores[(size_t)BB * LSEQ * NLP];    // 587 MB
__device__ float g_xr [(size_t)BB * LSEQ * DD];        // 64 MB rounded x
__device__ float g_xt [(size_t)BB * DD * LSEQ];        // 64 MB rounded x^T
__device__ float g_w1r[(size_t)DD * DD];               // 4 MB
__device__ float g_w2r[(size_t)NLP * DD];              // 36.7 MB rounded+padded W2
__device__ float g_pmax[BB * NSEG * NLP];
__device__ float g_psum[BB * NSEG * NLP];
__device__ float g_max [BB * NLP];
__device__ float g_rsum[BB * NLP];

// ======================= helpers ===========================================
__device__ __forceinline__ uint32_t smem_u32(const void* p) {
    uint32_t a;
    asm("{ .reg .u64 t; cvta.to.shared.u64 t, %1; cvt.u32.u64 %0, t; }"
        : "=r"(a) : "l"(p));
    return a;
}
__device__ __forceinline__ float f_rna_tf32(float v) {
    uint32_t r;
    asm("cvt.rna.tf32.f32 %0, %1;" : "=r"(r) : "f"(v));
    return __uint_as_float(r);
}
__device__ __forceinline__ void cp_async16(uint32_t dst, const void* src) {
    asm volatile("cp.async.cg.shared.global [%0], [%1], 16;"
        :: "r"(dst), "l"(src));
}
#define CP_COMMIT() asm volatile("cp.async.commit_group;" ::: "memory")
#define CP_WAIT(n)  asm volatile("cp.async.wait_group %0;" :: "n"(n) : "memory")

__device__ __forceinline__ void mma_tf32(float* c, const uint32_t* a, const uint32_t* b) {
    asm volatile(
        "mma.sync.aligned.m16n8k8.row.col.f32.tf32.tf32.f32 "
        "{%0,%1,%2,%3}, {%4,%5,%6,%7}, {%8,%9}, {%0,%1,%2,%3};"
        : "+f"(c[0]), "+f"(c[1]), "+f"(c[2]), "+f"(c[3])
        : "r"(a[0]), "r"(a[1]), "r"(a[2]), "r"(a[3]),
          "r"(b[0]), "r"(b[1]));
}

// ldmatrix x4 of 8x8 b16 tiles == four (8 row x 4 col) b32 mma quadrants
__device__ __forceinline__ void ldsm4(uint32_t& r0, uint32_t& r1,
                                      uint32_t& r2, uint32_t& r3, uint32_t addr) {
    asm volatile("ldmatrix.sync.aligned.m8n8.x4.shared.b16 {%0,%1,%2,%3}, [%4];"
        : "=r"(r0), "=r"(r1), "=r"(r2), "=r"(r3) : "r"(addr));
}

// smem float offset for element (r, k) of a 128x32 tile; XOR swizzle keeps
// 16B chunks intact and makes all fragment reads bank-conflict-free.
__device__ __forceinline__ int swoff(int r, int k) {
    return (r << 5) + (k ^ ((r & 7) << 2));
}

// ---------------------------------------------------------------------------
// tf32 mma.sync GEMM (NT): C[M x Nc] = A[M x K] @ B[* x K]^T
// B rows padded to grid width (unguarded). A rows clamped if CLAMP_A.
// Output rows guarded to Mv if GUARD_M. blockIdx.z = batch via strides.
// Fragment double-buffered: ldsm for k-step ks+1 issued before mmas of ks.
// ---------------------------------------------------------------------------
template <bool DO_TANH, bool GUARD_M, bool CLAMP_A>
__global__ __launch_bounds__(256, 2) void tc_gemm(
    const float* __restrict__ A, const float* __restrict__ Bm, float* __restrict__ C,
    int Mv, int Nc, int K, long sAb, long sBb, long sCb)
{
    extern __shared__ float smf[];
    const uint32_t sbase = smem_u32(smf);
    const int tid  = threadIdx.x;
    const int wid  = tid >> 5;
    const int lid  = tid & 31;
    const int g    = lid >> 2;
    const int tig  = lid & 3;
    const int wrow = wid >> 1;   // 0..3 (M, 32 rows each)
    const int wcol = wid & 1;    // 0..1 (N, 64 cols each)

    A  += (long)blockIdx.z * sAb;
    Bm += (long)blockIdx.z * sBb;
    C  += (long)blockIdx.z * sCb;

    const long row0 = (long)blockIdx.y * Bb;
    const long col0 = (long)blockIdx.x * BN;
    const int  nch  = K / BK;

    // tile-load mapping: 1024 float4 per operand, 4 per thread
    const int lr = tid >> 3;
    const int lc = tid & 7;

    // ldmatrix lane geometry (tile index = lid>>3)
    const int a_rin = ((lid >> 3) & 1) * 8 + (lid & 7);
    const int a_kg  = (lid >> 4) * 4;           // lanes 16-31 -> k+4
    const int b_rin = ((lid >> 4) & 1) * 8 + (lid & 7);
    const int b_kg  = ((lid >> 3) & 1) * 4;

    float acc[2][8][4];
    #pragma unroll
    for (int mt = 0; mt < 2; mt++)
        #pragma unroll
        for (int nt = 0; nt < 8; nt++)
            #pragma unroll
            for (int q = 0; q < 4; q++) acc[mt][nt][q] = 0.f;

    auto issue = [&](int i, int s) {
        const float* Ag = A + (long)i * BK;
        const float* Bg = Bm + col0 * K + (long)i * BK;
        uint32_t st = sbase + s * (STG_FLOATS * 4);
        #pragma unroll
        for (int t = 0; t < 4; t++) {
            int r = lr + t * 32;
            long rA = row0 + r;
            if (CLAMP_A && rA > Mv - 1) rA = Mv - 1;
            cp_async16(st + swoff(r, lc * 4) * 4, Ag + rA * K + lc * 4);
        }
        uint32_t stB = st + Bb * BK * 4;
        #pragma unroll
        for (int t = 0; t < 4; t++) {
            int r = lr + t * 32;
            cp_async16(stB + swoff(r, lc * 4) * 4, Bg + (long)r * K + lc * 4);
        }
    };

    auto load_frags = [&](uint32_t sAu, uint32_t sBu, int ks,
                          uint32_t (&af)[2][4], uint32_t (&bf)[8][2]) {
        const int kb = ks * 8;
        #pragma unroll
        for (int mt = 0; mt < 2; mt++) {
            int r = wrow * 32 + mt * 16 + a_rin;
            ldsm4(af[mt][0], af[mt][1], af[mt][2], af[mt][3],
                  sAu + 4u * swoff(r, kb + a_kg));
        }
        #pragma unroll
        for (int j = 0; j < 4; j++) {
            int r = wcol * 64 + j * 16 + b_rin;
            ldsm4(bf[2 * j][0], bf[2 * j][1], bf[2 * j + 1][0], bf[2 * j + 1][1],
                  sBu + 4u * swoff(r, kb + b_kg));
        }
    };

    #pragma unroll
    for (int i = 0; i < STAGES - 1; i++) { issue(i, i); CP_COMMIT(); }

    for (int i = 0; i < nch; i++) {
        CP_WAIT(STAGES - 2);
        __syncthreads();

        const int inext = i + STAGES - 1;
        if (inext < nch) issue(inext, inext % STAGES);
        CP_COMMIT();

        const uint32_t sAu = sbase + (i % STAGES) * (STG_FLOATS * 4);
        const uint32_t sBu = sAu + Bb * BK * 4;

        uint32_t af[2][2][4], bf[2][8][2];
        load_frags(sAu, sBu, 0, af[0], bf[0]);
        #pragma unroll
        for (int ks = 0; ks < 4; ks++) {
            const int cur = ks & 1;
            if (ks < 3)
                load_frags(sAu, sBu, ks + 1, af[cur ^ 1], bf[cur ^ 1]);
            #pragma unroll
            for (int mt = 0; mt < 2; mt++)
                #pragma unroll
                for (int nt = 0; nt < 8; nt++)
                    mma_tf32(acc[mt][nt], af[cur][mt], bf[cur][nt]);
        }
    }

    // epilogue: float2 stores, rows g and g+8 per m-tile
    #pragma unroll
    for (int mt = 0; mt < 2; mt++) {
        long r0 = row0 + wrow * 32 + mt * 16 + g;
        long r1 = r0 + 8;
        bool ok0 = !GUARD_M || (r0 < Mv);
        bool ok1 = !GUARD_M || (r1 < Mv);
        #pragma unroll
        for (int nt = 0; nt < 8; nt++) {
            long cc = col0 + wcol * 64 + nt * 8 + 2 * tig;
            float2 v0 = make_float2(acc[mt][nt][0], acc[mt][nt][1]);
            float2 v1 = make_float2(acc[mt][nt][2], acc[mt][nt][3]);
            if (DO_TANH) {
                v0.x = f_rna_tf32(tanhf(v0.x)); v0.y = f_rna_tf32(tanhf(v0.y));
                v1.x = f_rna_tf32(tanhf(v1.x)); v1.y = f_rna_tf32(tanhf(v1.y));
            }
            if (ok0) *reinterpret_cast<float2*>(&C[r0 * Nc + cc]) = v0;
            if (ok1) *reinterpret_cast<float2*>(&C[r1 * Nc + cc]) = v1;
        }
    }
}

// ---------------------------------------------------------------------------
// pre-round helpers
// ---------------------------------------------------------------------------
__global__ void roundcpy(const float* __restrict__ src, float* __restrict__ dst, int n)
{
    int i = blockIdx.x * 256 + threadIdx.x;
    if (i < n) dst[i] = f_rna_tf32(src[i]);
}
__global__ void w2pad(const float* __restrict__ W2, float* __restrict__ dst)
{
    int i = blockIdx.x * 256 + threadIdx.x;
    if (i >= NLP * DD) return;
    int row = i / DD;
    dst[i] = (row < NLBL) ? f_rna_tf32(W2[i]) : 0.f;
}

// ---------------------------------------------------------------------------
// xprep: read x once; write xr = rna(x) (same layout) and xT = rna(x)^T
// ---------------------------------------------------------------------------
__global__ void xprep(const float* __restrict__ x, float* __restrict__ xr,
                      float* __restrict__ xT)
{
    __shared__ float tile[32][33];
    int b  = blockIdx.z;
    int d0 = blockIdx.x * 32;
    int l0 = blockIdx.y * 32;
    int tx = threadIdx.x, ty = threadIdx.y;  // 32 x 8
    #pragma unroll
    for (int i = 0; i < 4; i++) {
        size_t idx = ((size_t)b * LSEQ + l0 + ty + i * 8) * DD + d0 + tx;
        float v = f_rna_tf32(x[idx]);
        xr[idx] = v;
        tile[ty + i * 8][tx] = v;
    }
    __syncthreads();
    #pragma unroll
    for (int i = 0; i < 4; i++)
        xT[((size_t)b * DD + d0 + ty + i * 8) * LSEQ + l0 + tx] = tile[tx][ty + i * 8];
}

// ---------------------------------------------------------------------------
// Softmax over L of scores[B, L, NLP] (valid cols < NLBL), segmented.
// ---------------------------------------------------------------------------
__global__ void softmax_part(const float* __restrict__ scores)
{
    int n = blockIdx.x * 256 + threadIdx.x;
    int s = blockIdx.y;
    int b = blockIdx.z;
    float m = -1e30f, sum = 0.f;
    if (n < NLBL) {
        const float* p = scores + ((size_t)b * LSEQ + (size_t)s * SEGL) * NLP + n;
        #pragma unroll 4
        for (int l = 0; l < SEGL; l++) {
            float v = p[(size_t)l * NLP];
            if (v <= m) {
                sum += __expf(v - m);
            } else {
                sum = sum * __expf(m - v) + 1.f;
                m = v;
            }
        }
    }
    g_pmax[(b * NSEG + s) * NLP + n] = m;
    g_psum[(b * NSEG + s) * NLP + n] = sum;
}

__global__ void softmax_comb()
{
    int n = blockIdx.x * 256 + threadIdx.x;
    int b = blockIdx.z;
    float m = -1e30f;
    #pragma unroll
    for (int s = 0; s < NSEG; s++)
        m = fmaxf(m, g_pmax[(b * NSEG + s) * NLP + n]);
    float sum = 0.f;
    #pragma unroll
    for (int s = 0; s < NSEG; s++)
        sum += g_psum[(b * NSEG + s) * NLP + n] * __expf(g_pmax[(b * NSEG + s) * NLP + n] - m);
    g_max [b * NLP + n] = m;
    g_rsum[b * NLP + n] = 1.f / sum;
}

// ---------------------------------------------------------------------------
// attn[b,n,l] = rna_tf32(exp(scores[b,l,n]-max)*rsum)  (single rounded copy;
// feeds both the output comparison and GEMM3)
// ---------------------------------------------------------------------------
__global__ void attn_transpose(const float* __restrict__ scores, float* __restrict__ attn)
{
    __shared__ float tile[32][33];
    int b  = blockIdx.z;
    int n0 = blockIdx.x * 32;
    int l0 = blockIdx.y * 32;
    int tx = threadIdx.x, ty = threadIdx.y;  // 32 x 8

    int n = n0 + tx;
    float m = 0.f, r = 0.f;
    if (n < NLBL) {
        m = g_max [b * NLP + n];
        r = g_rsum[b * NLP + n];
    }
    #pragma unroll
    for (int i = 0; i < 4; i++) {
        int l = l0 + ty + i * 8;
        float v = 0.f;
        if (n < NLBL)
            v = __expf(scores[((size_t)b * LSEQ + l) * NLP + n] - m) * r;
        tile[ty + i * 8][tx] = v;
    }
    __syncthreads();
    #pragma unroll
    for (int i = 0; i < 4; i++) {
        int n2 = n0 + ty + i * 8;
        int l  = l0 + tx;
        if (n2 < NLBL)
            attn[((size_t)b * NLBL + n2) * LSEQ + l] = f_rna_tf32(tile[tx][ty + i * 8]);
    }
}

// ---------------------------------------------------------------------------
extern "C" void kernel_launch(void* const* d_in, const int* in_sizes, int n_in,
                              void* d_out, int out_size)
{
    const float* x  = (const float*)d_in[0];   // [B, L, D]
    const float* W1 = (const float*)d_in[1];   // [D, D]
    const float* W2 = (const float*)d_in[2];   // [NL, D]

    float* out  = (float*)d_out;                          // [B, NL, D]
    float* attn = out + (size_t)BB * NLBL * DD;           // [B, NL, L]

    float *l1, *scores, *xr, *xt, *w1r, *w2r;
    cudaGetSymbolAddress((void**)&l1, g_l1);
    cudaGetSymbolAddress((void**)&scores, g_scores);
    cudaGetSymbolAddress((void**)&xr, g_xr);
    cudaGetSymbolAddress((void**)&xt, g_xt);
    cudaGetSymbolAddress((void**)&w1r, g_w1r);
    cudaGetSymbolAddress((void**)&w2r, g_w2r);

    const int SMEMB = SMEM_FLOATS * 4;  // 96 KB
    cudaFuncSetAttribute(tc_gemm<true,  false, false>, cudaFuncAttributeMaxDynamicSharedMemorySize, SMEMB);
    cudaFuncSetAttribute(tc_gemm<false, false, false>, cudaFuncAttributeMaxDynamicSharedMemorySize, SMEMB);
    cudaFuncSetAttribute(tc_gemm<false, true,  true >, cudaFuncAttributeMaxDynamicSharedMemorySize, SMEMB);

    // 0) pre-round operands to tf32 values (RNA); xprep also builds x^T
    xprep<<<dim3(DD / 32, LSEQ / 32, BB), dim3(32, 8)>>>(x, xr, xt);
    roundcpy<<<(DD * DD + 255) / 256, 256>>>(W1, w1r, DD * DD);
    w2pad<<<(NLP * DD + 255) / 256, 256>>>(W2, w2r);

    // 1) l1 = rna(tanh(xr @ w1r^T)):  M=16384, N=1024, K=1024
    tc_gemm<true, false, false><<<dim3(DD / BN, (BB * LSEQ) / Bb, 1), 256, SMEMB>>>(
        xr, w1r, l1, BB * LSEQ, DD, DD, 0, 0, 0);

    // 2) scores = l1 @ w2r^T:  M=16384, Nc=NLP, K=1024
    tc_gemm<false, false, false><<<dim3(NLP / BN, (BB * LSEQ) / Bb, 1), 256, SMEMB>>>(
        l1, w2r, scores, BB * LSEQ, NLP, DD, 0, 0, 0);

    // 3) column softmax stats over L
    softmax_part<<<dim3(NLP / 256, NSEG, BB), 256>>>(scores);
    softmax_comb<<<dim3(NLP / 256, 1, BB), 256>>>();

    // 4) attn = rna(softmax(scores)^T)  (single rounded copy, is the output)
    attn_transpose<<<dim3(NLP / 32, LSEQ / 32, BB), dim3(32, 8)>>>(scores, attn);

    // 5) out[b] = attn[b] @ xt[b]^T:  M=8921 (rows clamped), N=1024, K=4096
    tc_gemm<false, true, true><<<dim3(DD / BN, NLP / Bb, BB), 256, SMEMB>>>(
        attn, xt, out, NLBL, DD, LSEQ,
        (long)NLBL * LSEQ, (long)DD * LSEQ, (long)NLBL * DD);
}